// round 16
// baseline (speedup 1.0000x reference)
#include <cuda_runtime.h>
#include <cuda_fp16.h>
#include <cstdint>

#define NB 8
#define CC 64
#define HH 192
#define WW 192
#define HP 194
#define WP 194
#define NPIX (NB*HH*WW)      /* 294912 */
#define VOL  (NPIX*CC)       /* 18874368 */
#define HW   (HH*WW)         /* 36864 */

// ---------------- scratch (static device globals; zero-initialized) ----------------
__device__ int8_t g_A1[NB*HP*WP*CC];     // quantized act 1, NHWC, zero-padded halo
__device__ float  g_X1[VOL];             // conv1 output post-prelu, NHWC fp32 (feeds round())
__device__ __half g_Y2h[VOL];            // conv2 raw output, NCHW fp16 (affine-only downstream)
__device__ int8_t g_w1p[9*64*64];        // packed weights [tap][cout][cin] bytes
__device__ int8_t g_w2p[9*64*64];
__device__ float  g_S[2];                // combined conv scales (a_scale * w_scale)
__device__ double g_bn1s[CC], g_bn1q[CC], g_bn2s[CC], g_bn2q[CC];
__device__ float  g_c1s[CC], g_c1b[CC], g_c2s[CC], g_c2b[CC];

// ---------------- kernel 0: zero BN accumulators ----------------
__global__ void k_zero()
{
    int t = threadIdx.x;
    if (t < CC) { g_bn1s[t] = 0.0; g_bn1q[t] = 0.0; g_bn2s[t] = 0.0; g_bn2q[t] = 0.0; }
}

// ---------------- kernel 1: weight quantization ----------------
__global__ void k_wquant(const float* __restrict__ w1, const float* __restrict__ w2,
                         const float* __restrict__ a1, const float* __restrict__ a2)
{
    int b = blockIdx.x, t = threadIdx.x;
    const float* w = b ? w2 : w1;
    int8_t* wp = b ? g_w2p : g_w1p;
    __shared__ float red[256];
    float m = 0.f;
    for (int i = t; i < 36864; i += 256) m = fmaxf(m, fabsf(w[i]));
    red[t] = m; __syncthreads();
    for (int s = 128; s; s >>= 1) { if (t < s) red[t] = fmaxf(red[t], red[t+s]); __syncthreads(); }
    float sw = red[0] / 127.0f;
    if (t == 0) g_S[b] = ((b ? a2[0] : a1[0]) / 127.0f) * sw;
    for (int i = t; i < 36864; i += 256) {
        float q = rintf(w[i] / sw);
        q = fminf(fmaxf(q, -127.f), 127.f);
        int o = i / 576, ci = (i / 9) % 64, tap = i % 9;
        wp[(tap*64 + o)*64 + ci] = (int8_t)q;
    }
}

// ---------------- kernel 2: quantize identity, NCHW fp32 -> NHWC int8 (padded) -------
__global__ void k_quant1(const float* __restrict__ x, const float* __restrict__ a1p)
{
    __shared__ uchar4 sb[32][17];
    int w0 = blockIdx.x*32, h = blockIdx.y, n = blockIdx.z;
    int tx = threadIdx.x, ty = threadIdx.y;
    float al = a1p[0], sc = al / 127.0f;
    #pragma unroll
    for (int k = 0; k < 2; k++) {
        int cg = ty + 8*k;
        union { int8_t b[4]; uchar4 v; } u;
        #pragma unroll
        for (int j = 0; j < 4; j++) {
            int c = cg*4 + j;
            float xv = x[((n*CC + c)*HH + h)*WW + w0 + tx];
            xv = fminf(fmaxf(xv, -al), al);
            u.b[j] = (int8_t)(int)rintf(xv / sc);
        }
        sb[tx][cg] = u.v;
    }
    __syncthreads();
    int tid = ty*32 + tx;
    #pragma unroll
    for (int k = 0; k < 2; k++) {
        int uu = tid + 256*k;
        int p = uu >> 4, cg = uu & 15;
        *reinterpret_cast<uchar4*>(&g_A1[((n*HP + h+1)*WP + (w0+p+1))*64 + cg*4]) = sb[p][cg];
    }
}

// ---------------- dp4a tap (DW compile-time so swizzle XOR folds) --------------------
template<int DW>
__device__ __forceinline__ void dp4a_tap(const int4* __restrict__ sA,
                                         const int4* __restrict__ sW,
                                         int rs, int t, int tx, int pb, int* acc)
{
    const int4* ar = sA + (rs*66 + pb + DW)*4;
    #pragma unroll
    for (int cg = 0; cg < 4; cg++) {
        int4 wv = sW[(t*64 + tx)*4 + (cg ^ ((tx & 6) >> 1))];
        #pragma unroll
        for (int k = 0; k < 16; k++) {
            int4 av = ar[k*4 + (cg ^ (((DW + k) & 6) >> 1))];  // pb%16==0
            acc[k] = __dp4a(av.x, wv.x, acc[k]);
            acc[k] = __dp4a(av.y, wv.y, acc[k]);
            acc[k] = __dp4a(av.z, wv.z, acc[k]);
            acc[k] = __dp4a(av.w, wv.w, acc[k]);
        }
    }
}

// ---------------- conv1: hybrid IMMA (warps 0-3, row 0) + dp4a (warps 4-11, row 1) ---
// Block 384 thr; tile 2 rows x 64 pix x 64 couts; grid (3, 96, 8). (R15, unchanged)
__global__ void __launch_bounds__(384) k_conv1(const float* __restrict__ pa_p)
{
    extern __shared__ int4 smem[];
    int4* sA = smem;                 // 4 rows x 66 pix x 4 = 1056 int4
    int4* sW = smem + 1056;          // 2304 int4
    __shared__ float ss[64], sq[64];
    const uint32_t* sAw = (const uint32_t*)sA;
    const uint32_t* sWw = (const uint32_t*)sW;

    const int4* W4 = (const int4*)g_w1p;
    int tid = threadIdx.x;
    int lane = tid & 31, warp = tid >> 5;
    int w0 = blockIdx.x*64, H0 = blockIdx.y*2, n = blockIdx.z;

    if (tid < 64) { ss[tid] = 0.f; sq[tid] = 0.f; }

    const int4* A4 = (const int4*)g_A1;
    for (int u = tid; u < 1056; u += 384) {
        int r = u / 264, rem = u % 264, pix = rem >> 2, c4 = rem & 3;
        sA[(r*66 + pix)*4 + (c4 ^ ((pix & 6) >> 1))] =
            A4[((n*HP + H0 + r)*WP + w0 + pix)*4 + c4];
    }
    for (int u = tid; u < 2304; u += 384) {
        int c4 = u & 3, co = (u >> 2) & 63, t = u >> 8;
        sW[(t*64 + co)*4 + (c4 ^ ((co & 6) >> 1))] = W4[u];
    }
    __syncthreads();

    float S  = g_S[0];
    float pa = pa_p[0];

    if (warp < 4) {
        int g = lane >> 2, t4 = lane & 3;
        int pbI = warp * 16;

        int acc[8][4];
        #pragma unroll
        for (int o = 0; o < 8; o++)
            #pragma unroll
            for (int j = 0; j < 4; j++) acc[o][j] = 0;

        #pragma unroll 1
        for (int t = 0; t < 9; t++) {
            int dh = t / 3, dw = t % 3;
            int p0 = pbI + g + dw;
            uint32_t af[2][4];
            #pragma unroll
            for (int c = 0; c < 2; c++) {
                int cin = 32*c + 4*t4;
                int off = (dh*66 + p0)*16 + ((cin ^ ((p0 & 6) << 3)) >> 2);
                af[c][0] = sAw[off];
                af[c][1] = sAw[off + 128];
                af[c][2] = sAw[off ^ 4];
                af[c][3] = sAw[(off + 128) ^ 4];
            }
            #pragma unroll
            for (int c = 0; c < 2; c++) {
                int cin = 32*c + 4*t4;
                #pragma unroll
                for (int o = 0; o < 8; o++) {
                    int co = o*8 + g;
                    int boff = (t*64 + co)*16 + ((cin ^ ((co & 6) << 3)) >> 2);
                    uint32_t b0 = sWw[boff];
                    uint32_t b1 = sWw[boff ^ 4];
                    asm volatile(
                        "mma.sync.aligned.m16n8k32.row.col.s32.s8.s8.s32 "
                        "{%0,%1,%2,%3},{%4,%5,%6,%7},{%8,%9},{%0,%1,%2,%3};"
                        : "+r"(acc[o][0]), "+r"(acc[o][1]),
                          "+r"(acc[o][2]), "+r"(acc[o][3])
                        : "r"(af[c][0]), "r"(af[c][1]), "r"(af[c][2]), "r"(af[c][3]),
                          "r"(b0), "r"(b1));
                }
            }
        }

        float sj[8][2], qj[8][2];
        #pragma unroll
        for (int o = 0; o < 8; o++) { sj[o][0]=sj[o][1]=qj[o][0]=qj[o][1]=0.f; }

        int pixl = H0*WW + w0 + pbI;
        #pragma unroll
        for (int o = 0; o < 8; o++) {
            int col = o*8 + 2*t4;
            float y0 = S * (float)acc[o][0];
            float y1 = S * (float)acc[o][1];
            float y2 = S * (float)acc[o][2];
            float y3 = S * (float)acc[o][3];
            y0 = (y0 >= 0.f) ? y0 : pa*y0;
            y1 = (y1 >= 0.f) ? y1 : pa*y1;
            y2 = (y2 >= 0.f) ? y2 : pa*y2;
            y3 = (y3 >= 0.f) ? y3 : pa*y3;
            int row0 = n*HW + pixl + g, row1 = row0 + 8;
            *reinterpret_cast<float2*>(&g_X1[(size_t)row0*64 + col]) = make_float2(y0, y1);
            *reinterpret_cast<float2*>(&g_X1[(size_t)row1*64 + col]) = make_float2(y2, y3);
            sj[o][0] += y0 + y2;  qj[o][0] += y0*y0 + y2*y2;
            sj[o][1] += y1 + y3;  qj[o][1] += y1*y1 + y3*y3;
        }
        #pragma unroll
        for (int o = 0; o < 8; o++) {
            #pragma unroll
            for (int j = 0; j < 2; j++) {
                float s = sj[o][j], q = qj[o][j];
                #pragma unroll
                for (int off = 4; off < 32; off <<= 1) {
                    s += __shfl_xor_sync(0xffffffffu, s, off);
                    q += __shfl_xor_sync(0xffffffffu, q, off);
                }
                if (g == 0) {
                    int chan = o*8 + t4*2 + j;
                    atomicAdd(&ss[chan], s);
                    atomicAdd(&sq[chan], q);
                }
            }
        }
    } else {
        int tid2 = tid - 128;
        int tx = tid2 & 63;
        int ty = tid2 >> 6;
        int pb = ty * 16;

        int acc[16];
        #pragma unroll
        for (int k = 0; k < 16; k++) acc[k] = 0;

        #pragma unroll 1
        for (int t = 0; t < 9; t++) {
            int dh = t / 3, dw = t % 3;
            int rs = 1 + dh;
            switch (dw) {
                case 0: dp4a_tap<0>(sA, sW, rs, t, tx, pb, acc); break;
                case 1: dp4a_tap<1>(sA, sW, rs, t, tx, pb, acc); break;
                default: dp4a_tap<2>(sA, sW, rs, t, tx, pb, acc); break;
            }
        }

        int pixl = (H0 + 1)*WW + w0 + pb;
        float s = 0.f, q = 0.f;
        #pragma unroll
        for (int k = 0; k < 16; k++) {
            float y = S * (float)acc[k];
            y = (y >= 0.f) ? y : pa*y;
            g_X1[(size_t)(n*HW + pixl + k)*64 + tx] = y;
            s += y; q += y*y;
        }
        atomicAdd(&ss[tx], s);
        atomicAdd(&sq[tx], q);
    }

    __syncthreads();
    if (tid < 64) {
        atomicAdd(&g_bn1s[tid], (double)ss[tid]);
        atomicAdd(&g_bn1q[tid], (double)sq[tid]);
    }
}

// ---------------- conv2: 4-row hybrid ------------------------------------------------
// Block 640 thr = 20 warps; grid (3, 48, 8). Fused BN1+quant staging (6 halo rows).
// Warps 0-11 : IMMA (16 pix x 64 cout each), rows 0-2. Warps 12-19: dp4a, row 3.
__global__ void __launch_bounds__(640, 1) k_conv2(const float* __restrict__ a2p)
{
    extern __shared__ int4 smem[];
    int4* sA = smem;                 // 6 rows x 66 pix x 4 = 1584 int4
    int4* sW = smem + 1584;          // 2304 int4
    __shared__ float ss[64], sq[64];
    __shared__ float sc1[64], sb1[64];
    const uint32_t* sAw = (const uint32_t*)sA;
    const uint32_t* sWw = (const uint32_t*)sW;

    const int4* W4 = (const int4*)g_w2p;
    int tid = threadIdx.x;
    int lane = tid & 31, warp = tid >> 5;
    int w0 = blockIdx.x*64, H0 = blockIdx.y*4, n = blockIdx.z;

    if (tid < 64) {
        ss[tid] = 0.f; sq[tid] = 0.f;
        sc1[tid] = g_c1s[tid]; sb1[tid] = g_c1b[tid];
    }
    __syncthreads();
    float al = a2p[0], sc = al / 127.0f;
    for (int u = tid; u < 1584; u += 640) {
        int r = u / 264, rem = u % 264, pix = rem >> 2, c4 = rem & 3;
        int hr = H0 + r - 1, wc = w0 + pix - 1;
        union { int8_t b[16]; int4 v; } pk;
        pk.v = make_int4(0, 0, 0, 0);
        if (hr >= 0 && hr < HH && wc >= 0 && wc < WW) {
            const float4* src = reinterpret_cast<const float4*>(
                &g_X1[(size_t)((n*HW + hr*WW + wc)*64 + c4*16)]);
            #pragma unroll
            for (int q2 = 0; q2 < 4; q2++) {
                float4 v = src[q2];
                int cb = c4*16 + q2*4;
                float vv[4] = {v.x, v.y, v.z, v.w};
                #pragma unroll
                for (int j = 0; j < 4; j++) {
                    float t = vv[j]*sc1[cb+j] + sb1[cb+j];
                    t = fminf(fmaxf(t, -al), al);
                    pk.b[q2*4 + j] = (int8_t)(int)rintf(t / sc);
                }
            }
        }
        sA[(r*66 + pix)*4 + (c4 ^ ((pix & 6) >> 1))] = pk.v;
    }
    for (int u = tid; u < 2304; u += 640) {
        int c4 = u & 3, co = (u >> 2) & 63, t = u >> 8;
        sW[(t*64 + co)*4 + (c4 ^ ((co & 6) >> 1))] = W4[u];
    }
    __syncthreads();

    float S = g_S[1];

    if (warp < 12) {
        // ===== IMMA engine: rows 0-2 (warp: lrow = warp>>2, colb = (warp&3)*16) =====
        int g = lane >> 2, t4 = lane & 3;
        int lrow = warp >> 2;
        int colb = (warp & 3) * 16;

        int acc[8][4];
        #pragma unroll
        for (int o = 0; o < 8; o++)
            #pragma unroll
            for (int j = 0; j < 4; j++) acc[o][j] = 0;

        #pragma unroll 1
        for (int t = 0; t < 9; t++) {
            int dh = t / 3, dw = t % 3;
            int rs = lrow + dh;
            int p0 = colb + g + dw;
            uint32_t af[2][4];
            #pragma unroll
            for (int c = 0; c < 2; c++) {
                int cin = 32*c + 4*t4;
                int off = (rs*66 + p0)*16 + ((cin ^ ((p0 & 6) << 3)) >> 2);
                af[c][0] = sAw[off];
                af[c][1] = sAw[off + 128];
                af[c][2] = sAw[off ^ 4];
                af[c][3] = sAw[(off + 128) ^ 4];
            }
            #pragma unroll
            for (int c = 0; c < 2; c++) {
                int cin = 32*c + 4*t4;
                #pragma unroll
                for (int o = 0; o < 8; o++) {
                    int co = o*8 + g;
                    int boff = (t*64 + co)*16 + ((cin ^ ((co & 6) << 3)) >> 2);
                    uint32_t b0 = sWw[boff];
                    uint32_t b1 = sWw[boff ^ 4];
                    asm volatile(
                        "mma.sync.aligned.m16n8k32.row.col.s32.s8.s8.s32 "
                        "{%0,%1,%2,%3},{%4,%5,%6,%7},{%8,%9},{%0,%1,%2,%3};"
                        : "+r"(acc[o][0]), "+r"(acc[o][1]),
                          "+r"(acc[o][2]), "+r"(acc[o][3])
                        : "r"(af[c][0]), "r"(af[c][1]), "r"(af[c][2]), "r"(af[c][3]),
                          "r"(b0), "r"(b1));
                }
            }
        }

        float sj[8][2], qj[8][2];
        #pragma unroll
        for (int o = 0; o < 8; o++) { sj[o][0]=sj[o][1]=qj[o][0]=qj[o][1]=0.f; }

        int pixl = (H0 + lrow)*WW + w0 + colb;
        bool geven = (g & 1) == 0;
        #pragma unroll
        for (int o = 0; o < 8; o++) {
            int col = o*8 + 2*t4;
            float y0 = S * (float)acc[o][0];
            float y1 = S * (float)acc[o][1];
            float y2 = S * (float)acc[o][2];
            float y3 = S * (float)acc[o][3];
            float y0n = __shfl_xor_sync(0xffffffffu, y0, 4);
            float y1n = __shfl_xor_sync(0xffffffffu, y1, 4);
            float y2n = __shfl_xor_sync(0xffffffffu, y2, 4);
            float y3n = __shfl_xor_sync(0xffffffffu, y3, 4);
            int b0 = (n*64 + col)*HW + pixl;
            int b1 = b0 + HW;
            int addrA = geven ? (b0 + g)     : (b1 + g - 1);
            int addrB = geven ? (b0 + 8 + g) : (b1 + 7 + g);
            __half2 vA = geven ? __floats2half2_rn(y0, y0n) : __floats2half2_rn(y1n, y1);
            __half2 vB = geven ? __floats2half2_rn(y2, y2n) : __floats2half2_rn(y3n, y3);
            *reinterpret_cast<__half2*>(&g_Y2h[addrA]) = vA;
            *reinterpret_cast<__half2*>(&g_Y2h[addrB]) = vB;
            sj[o][0] += y0 + y2;  qj[o][0] += y0*y0 + y2*y2;
            sj[o][1] += y1 + y3;  qj[o][1] += y1*y1 + y3*y3;
        }
        #pragma unroll
        for (int o = 0; o < 8; o++) {
            #pragma unroll
            for (int j = 0; j < 2; j++) {
                float s = sj[o][j], q = qj[o][j];
                #pragma unroll
                for (int off = 4; off < 32; off <<= 1) {
                    s += __shfl_xor_sync(0xffffffffu, s, off);
                    q += __shfl_xor_sync(0xffffffffu, q, off);
                }
                if (g == 0) {
                    int chan = o*8 + t4*2 + j;
                    atomicAdd(&ss[chan], s);
                    atomicAdd(&sq[chan], q);
                }
            }
        }
    } else {
        // ===== dp4a engine: row 3 =====
        int tid2 = tid - 384;
        int tx = tid2 & 63;
        int ty = tid2 >> 6;
        int pb = ty * 16;

        int acc[16];
        #pragma unroll
        for (int k = 0; k < 16; k++) acc[k] = 0;

        #pragma unroll 1
        for (int t = 0; t < 9; t++) {
            int dh = t / 3, dw = t % 3;
            int rs = 3 + dh;
            switch (dw) {
                case 0: dp4a_tap<0>(sA, sW, rs, t, tx, pb, acc); break;
                case 1: dp4a_tap<1>(sA, sW, rs, t, tx, pb, acc); break;
                default: dp4a_tap<2>(sA, sW, rs, t, tx, pb, acc); break;
            }
        }

        int pixl = (H0 + 3)*WW + w0 + pb;
        float s = 0.f, q = 0.f;
        union { __half h[16]; int4 v[2]; } ob;
        #pragma unroll
        for (int k = 0; k < 16; k++) {
            float y = S * (float)acc[k];
            ob.h[k] = __float2half_rn(y);
            s += y; q += y*y;
        }
        int4* dst = reinterpret_cast<int4*>(&g_Y2h[(size_t)(n*64 + tx)*HW + pixl]);
        dst[0] = ob.v[0];
        dst[1] = ob.v[1];
        atomicAdd(&ss[tx], s);
        atomicAdd(&sq[tx], q);
    }

    __syncthreads();
    if (tid < 64) {
        atomicAdd(&g_bn2s[tid], (double)ss[tid]);
        atomicAdd(&g_bn2q[tid], (double)sq[tid]);
    }
}

// ---------------- BN stats finalize ----------------
template<bool FIRST>
__global__ void k_stats(const float* __restrict__ gamma, const float* __restrict__ beta)
{
    int c = threadIdx.x;
    const double* bs = FIRST ? g_bn1s : g_bn2s;
    const double* bq = FIRST ? g_bn1q : g_bn2q;
    double invn = 1.0 / (double)NPIX;
    double mean = bs[c] * invn;
    double var  = bq[c] * invn - mean*mean;
    float scl = gamma[c] * rsqrtf((float)var + 1e-5f);
    if (FIRST) { g_c1s[c] = scl; g_c1b[c] = beta[c] - (float)mean * scl; }
    else       { g_c2s[c] = scl; g_c2b[c] = beta[c] - (float)mean * scl; }
}

// ---------------- final elementwise, MLP=8 (R14, unchanged) ----------------
__global__ void k_final(const float* __restrict__ idn, const float* __restrict__ shortcut,
                        float* __restrict__ out, const float* __restrict__ bits,
                        const float* __restrict__ f, const float* __restrict__ bout,
                        int out_size)
{
    int c = blockIdx.y, n = blockIdx.z;
    int base = ((n*CC + c)*HW >> 2) + blockIdx.x*1024 + threadIdx.x;   // float4 index
    float scl = g_c2s[c], sft = g_c2b[c], sh = shortcut[0];
    const uint2* Y2v = reinterpret_cast<const uint2*>(g_Y2h);
    const float4* I4 = reinterpret_cast<const float4*>(idn);
    float4* O4 = reinterpret_cast<float4*>(out);

    uint2 y[4];
    float4 v[4];
    #pragma unroll
    for (int k = 0; k < 4; k++) {
        int i = base + k*256;
        y[k] = Y2v[i];
        v[k] = I4[i];
    }
    #pragma unroll
    for (int k = 0; k < 4; k++) {
        __half2 ha = *reinterpret_cast<__half2*>(&y[k].x);
        __half2 hb = *reinterpret_cast<__half2*>(&y[k].y);
        float2 ya = __half22float2(ha);
        float2 yb = __half22float2(hb);
        float4 r;
        r.x = v[k].x*sh + ya.x*scl + sft;
        r.y = v[k].y*sh + ya.y*scl + sft;
        r.z = v[k].z*sh + yb.x*scl + sft;
        r.w = v[k].w*sh + yb.y*scl + sft;
        O4[base + k*256] = r;
    }
    if (blockIdx.x == 0 && blockIdx.y == 0 && blockIdx.z == 0 && threadIdx.x == 0
        && out_size >= VOL + 3) {
        out[VOL]   = bits[0];
        out[VOL+1] = f[0];
        out[VOL+2] = bout[0];
    }
}

// ---------------- launch ----------------
extern "C" void kernel_launch(void* const* d_in, const int* in_sizes, int n_in,
                              void* d_out, int out_size)
{
    (void)in_sizes; (void)n_in;
    const float* identity = (const float*)d_in[0];
    const float* bits     = (const float*)d_in[1];
    const float* f        = (const float*)d_in[2];
    const float* bits_out = (const float*)d_in[3];
    const float* w1       = (const float*)d_in[4];
    const float* w2       = (const float*)d_in[5];
    const float* alpha1   = (const float*)d_in[6];
    const float* alpha2   = (const float*)d_in[7];
    const float* gamma1   = (const float*)d_in[8];
    const float* beta1    = (const float*)d_in[9];
    const float* gamma2   = (const float*)d_in[10];
    const float* beta2    = (const float*)d_in[11];
    const float* prelu_a  = (const float*)d_in[12];
    const float* shortcut = (const float*)d_in[13];
    float* out = (float*)d_out;

    const int SMEM1 = (1056 + 2304) * 16;  // 53760 B  (conv1 hybrid, 2-row)
    const int SMEM2 = (1584 + 2304) * 16;  // 62208 B  (conv2 hybrid, 4-row)
    cudaFuncSetAttribute(k_conv1, cudaFuncAttributeMaxDynamicSharedMemorySize, SMEM1);
    cudaFuncSetAttribute(k_conv2, cudaFuncAttributeMaxDynamicSharedMemorySize, SMEM2);

    k_zero<<<1, 64>>>();
    k_wquant<<<2, 256>>>(w1, w2, alpha1, alpha2);
    k_quant1<<<dim3(6,192,8), dim3(32,8)>>>(identity, alpha1);
    k_conv1<<<dim3(3,96,8), 384, SMEM1>>>(prelu_a);
    k_stats<true><<<1, 64>>>(gamma1, beta1);
    k_conv2<<<dim3(3,48,8), 640, SMEM2>>>(alpha2);
    k_stats<false><<<1, 64>>>(gamma2, beta2);
    k_final<<<dim3(HW/4/1024, CC, NB), 256>>>(identity, shortcut, out, bits, f, bits_out, out_size);
}

// round 17
// speedup vs baseline: 1.0836x; 1.0836x over previous
#include <cuda_runtime.h>
#include <cuda_fp16.h>
#include <cstdint>

#define NB 8
#define CC 64
#define HH 192
#define WW 192
#define HP 194
#define WP 194
#define NPIX (NB*HH*WW)      /* 294912 */
#define VOL  (NPIX*CC)       /* 18874368 */
#define HW   (HH*WW)         /* 36864 */

// ---------------- scratch (static device globals; zero-initialized) ----------------
__device__ int8_t g_A1[NB*HP*WP*CC];     // quantized act 1, NHWC, zero-padded halo
__device__ float  g_X1[VOL];             // conv1 output post-prelu, NHWC fp32 (feeds round())
__device__ __half g_Y2h[VOL];            // conv2 raw output, NCHW fp16 (affine-only downstream)
__device__ int8_t g_w1p[9*64*64];        // packed weights [tap][cout][cin] bytes
__device__ int8_t g_w2p[9*64*64];
__device__ float  g_S[2];                // combined conv scales (a_scale * w_scale)
__device__ double g_bn1s[CC], g_bn1q[CC], g_bn2s[CC], g_bn2q[CC];
__device__ float  g_c1s[CC], g_c1b[CC], g_c2s[CC], g_c2b[CC];

// ---------------- kernel 1: weight quantization + BN accumulator zeroing -------------
__global__ void k_wquant(const float* __restrict__ w1, const float* __restrict__ w2,
                         const float* __restrict__ a1, const float* __restrict__ a2)
{
    int b = blockIdx.x, t = threadIdx.x;
    if (b == 2) {
        if (t < CC) { g_bn1s[t] = 0.0; g_bn1q[t] = 0.0; g_bn2s[t] = 0.0; g_bn2q[t] = 0.0; }
        return;
    }
    const float* w = b ? w2 : w1;
    int8_t* wp = b ? g_w2p : g_w1p;
    __shared__ float red[256];
    float m = 0.f;
    for (int i = t; i < 36864; i += 256) m = fmaxf(m, fabsf(w[i]));
    red[t] = m; __syncthreads();
    for (int s = 128; s; s >>= 1) { if (t < s) red[t] = fmaxf(red[t], red[t+s]); __syncthreads(); }
    float sw = red[0] / 127.0f;
    if (t == 0) g_S[b] = ((b ? a2[0] : a1[0]) / 127.0f) * sw;
    for (int i = t; i < 36864; i += 256) {
        float q = rintf(w[i] / sw);
        q = fminf(fmaxf(q, -127.f), 127.f);
        int o = i / 576, ci = (i / 9) % 64, tap = i % 9;
        wp[(tap*64 + o)*64 + ci] = (int8_t)q;
    }
}

// ---------------- kernel 2: quantize identity, NCHW fp32 -> NHWC int8 (padded) -------
__global__ void k_quant1(const float* __restrict__ x, const float* __restrict__ a1p)
{
    __shared__ uchar4 sb[32][17];
    int w0 = blockIdx.x*32, h = blockIdx.y, n = blockIdx.z;
    int tx = threadIdx.x, ty = threadIdx.y;
    float al = a1p[0], sc = al / 127.0f;
    #pragma unroll
    for (int k = 0; k < 2; k++) {
        int cg = ty + 8*k;
        union { int8_t b[4]; uchar4 v; } u;
        #pragma unroll
        for (int j = 0; j < 4; j++) {
            int c = cg*4 + j;
            float xv = x[((n*CC + c)*HH + h)*WW + w0 + tx];
            xv = fminf(fmaxf(xv, -al), al);
            u.b[j] = (int8_t)(int)rintf(xv / sc);
        }
        sb[tx][cg] = u.v;
    }
    __syncthreads();
    int tid = ty*32 + tx;
    #pragma unroll
    for (int k = 0; k < 2; k++) {
        int uu = tid + 256*k;
        int p = uu >> 4, cg = uu & 15;
        *reinterpret_cast<uchar4*>(&g_A1[((n*HP + h+1)*WP + (w0+p+1))*64 + cg*4]) = sb[p][cg];
    }
}

// ---------------- dp4a tap (DW compile-time so swizzle XOR folds) --------------------
template<int DW>
__device__ __forceinline__ void dp4a_tap(const int4* __restrict__ sA,
                                         const int4* __restrict__ sW,
                                         int rs, int t, int tx, int pb, int* acc)
{
    const int4* ar = sA + (rs*66 + pb + DW)*4;
    #pragma unroll
    for (int cg = 0; cg < 4; cg++) {
        int4 wv = sW[(t*64 + tx)*4 + (cg ^ ((tx & 6) >> 1))];
        #pragma unroll
        for (int k = 0; k < 16; k++) {
            int4 av = ar[k*4 + (cg ^ (((DW + k) & 6) >> 1))];  // pb%16==0
            acc[k] = __dp4a(av.x, wv.x, acc[k]);
            acc[k] = __dp4a(av.y, wv.y, acc[k]);
            acc[k] = __dp4a(av.z, wv.z, acc[k]);
            acc[k] = __dp4a(av.w, wv.w, acc[k]);
        }
    }
}

// ---------------- conv1: hybrid IMMA (warps 0-3, row 0) + dp4a (warps 4-11, row 1) ---
// Block 384 thr; tile 2 rows x 64 pix x 64 couts; grid (3, 96, 8). (R15, measured 145.8us)
__global__ void __launch_bounds__(384) k_conv1(const float* __restrict__ pa_p)
{
    extern __shared__ int4 smem[];
    int4* sA = smem;                 // 4 rows x 66 pix x 4 = 1056 int4
    int4* sW = smem + 1056;          // 2304 int4
    __shared__ float ss[64], sq[64];
    const uint32_t* sAw = (const uint32_t*)sA;
    const uint32_t* sWw = (const uint32_t*)sW;

    const int4* W4 = (const int4*)g_w1p;
    int tid = threadIdx.x;
    int lane = tid & 31, warp = tid >> 5;
    int w0 = blockIdx.x*64, H0 = blockIdx.y*2, n = blockIdx.z;

    if (tid < 64) { ss[tid] = 0.f; sq[tid] = 0.f; }

    const int4* A4 = (const int4*)g_A1;
    for (int u = tid; u < 1056; u += 384) {
        int r = u / 264, rem = u % 264, pix = rem >> 2, c4 = rem & 3;
        sA[(r*66 + pix)*4 + (c4 ^ ((pix & 6) >> 1))] =
            A4[((n*HP + H0 + r)*WP + w0 + pix)*4 + c4];
    }
    for (int u = tid; u < 2304; u += 384) {
        int c4 = u & 3, co = (u >> 2) & 63, t = u >> 8;
        sW[(t*64 + co)*4 + (c4 ^ ((co & 6) >> 1))] = W4[u];
    }
    __syncthreads();

    float S  = g_S[0];
    float pa = pa_p[0];

    if (warp < 4) {
        int g = lane >> 2, t4 = lane & 3;
        int pbI = warp * 16;

        int acc[8][4];
        #pragma unroll
        for (int o = 0; o < 8; o++)
            #pragma unroll
            for (int j = 0; j < 4; j++) acc[o][j] = 0;

        #pragma unroll 1
        for (int t = 0; t < 9; t++) {
            int dh = t / 3, dw = t % 3;
            int p0 = pbI + g + dw;
            uint32_t af[2][4];
            #pragma unroll
            for (int c = 0; c < 2; c++) {
                int cin = 32*c + 4*t4;
                int off = (dh*66 + p0)*16 + ((cin ^ ((p0 & 6) << 3)) >> 2);
                af[c][0] = sAw[off];
                af[c][1] = sAw[off + 128];
                af[c][2] = sAw[off ^ 4];
                af[c][3] = sAw[(off + 128) ^ 4];
            }
            #pragma unroll
            for (int c = 0; c < 2; c++) {
                int cin = 32*c + 4*t4;
                #pragma unroll
                for (int o = 0; o < 8; o++) {
                    int co = o*8 + g;
                    int boff = (t*64 + co)*16 + ((cin ^ ((co & 6) << 3)) >> 2);
                    uint32_t b0 = sWw[boff];
                    uint32_t b1 = sWw[boff ^ 4];
                    asm volatile(
                        "mma.sync.aligned.m16n8k32.row.col.s32.s8.s8.s32 "
                        "{%0,%1,%2,%3},{%4,%5,%6,%7},{%8,%9},{%0,%1,%2,%3};"
                        : "+r"(acc[o][0]), "+r"(acc[o][1]),
                          "+r"(acc[o][2]), "+r"(acc[o][3])
                        : "r"(af[c][0]), "r"(af[c][1]), "r"(af[c][2]), "r"(af[c][3]),
                          "r"(b0), "r"(b1));
                }
            }
        }

        float sj[8][2], qj[8][2];
        #pragma unroll
        for (int o = 0; o < 8; o++) { sj[o][0]=sj[o][1]=qj[o][0]=qj[o][1]=0.f; }

        int pixl = H0*WW + w0 + pbI;
        #pragma unroll
        for (int o = 0; o < 8; o++) {
            int col = o*8 + 2*t4;
            float y0 = S * (float)acc[o][0];
            float y1 = S * (float)acc[o][1];
            float y2 = S * (float)acc[o][2];
            float y3 = S * (float)acc[o][3];
            y0 = (y0 >= 0.f) ? y0 : pa*y0;
            y1 = (y1 >= 0.f) ? y1 : pa*y1;
            y2 = (y2 >= 0.f) ? y2 : pa*y2;
            y3 = (y3 >= 0.f) ? y3 : pa*y3;
            int row0 = n*HW + pixl + g, row1 = row0 + 8;
            *reinterpret_cast<float2*>(&g_X1[(size_t)row0*64 + col]) = make_float2(y0, y1);
            *reinterpret_cast<float2*>(&g_X1[(size_t)row1*64 + col]) = make_float2(y2, y3);
            sj[o][0] += y0 + y2;  qj[o][0] += y0*y0 + y2*y2;
            sj[o][1] += y1 + y3;  qj[o][1] += y1*y1 + y3*y3;
        }
        #pragma unroll
        for (int o = 0; o < 8; o++) {
            #pragma unroll
            for (int j = 0; j < 2; j++) {
                float s = sj[o][j], q = qj[o][j];
                #pragma unroll
                for (int off = 4; off < 32; off <<= 1) {
                    s += __shfl_xor_sync(0xffffffffu, s, off);
                    q += __shfl_xor_sync(0xffffffffu, q, off);
                }
                if (g == 0) {
                    int chan = o*8 + t4*2 + j;
                    atomicAdd(&ss[chan], s);
                    atomicAdd(&sq[chan], q);
                }
            }
        }
    } else {
        int tid2 = tid - 128;
        int tx = tid2 & 63;
        int ty = tid2 >> 6;
        int pb = ty * 16;

        int acc[16];
        #pragma unroll
        for (int k = 0; k < 16; k++) acc[k] = 0;

        #pragma unroll 1
        for (int t = 0; t < 9; t++) {
            int dh = t / 3, dw = t % 3;
            int rs = 1 + dh;
            switch (dw) {
                case 0: dp4a_tap<0>(sA, sW, rs, t, tx, pb, acc); break;
                case 1: dp4a_tap<1>(sA, sW, rs, t, tx, pb, acc); break;
                default: dp4a_tap<2>(sA, sW, rs, t, tx, pb, acc); break;
            }
        }

        int pixl = (H0 + 1)*WW + w0 + pb;
        float s = 0.f, q = 0.f;
        #pragma unroll
        for (int k = 0; k < 16; k++) {
            float y = S * (float)acc[k];
            y = (y >= 0.f) ? y : pa*y;
            g_X1[(size_t)(n*HW + pixl + k)*64 + tx] = y;
            s += y; q += y*y;
        }
        atomicAdd(&ss[tx], s);
        atomicAdd(&sq[tx], q);
    }

    __syncthreads();
    if (tid < 64) {
        atomicAdd(&g_bn1s[tid], (double)ss[tid]);
        atomicAdd(&g_bn1q[tid], (double)sq[tid]);
    }
}

// ---------------- conv2: IMMA-only 4-row tile, fused BN1+quant staging (R15) ---------
// Block 512 thr = 16 warps; tile 256 pixels x 64 couts; grid (3, 48, 8).
__global__ void __launch_bounds__(512) k_conv2(const float* __restrict__ a2p)
{
    extern __shared__ int4 smem[];
    int4* sA = smem;                 // 1584 int4
    int4* sW = smem + 1584;          // 2304 int4
    __shared__ float ss[64], sq[64];
    __shared__ float sc1[64], sb1[64];
    const uint32_t* sAw = (const uint32_t*)sA;
    const uint32_t* sWw = (const uint32_t*)sW;

    const int4* W4 = (const int4*)g_w2p;
    int tid = threadIdx.x;
    int lane = tid & 31, warp = tid >> 5;
    int w0 = blockIdx.x*64, H0 = blockIdx.y*4, n = blockIdx.z;

    if (tid < 64) {
        ss[tid] = 0.f; sq[tid] = 0.f;
        sc1[tid] = g_c1s[tid]; sb1[tid] = g_c1b[tid];
    }
    __syncthreads();
    float al = a2p[0], sc = al / 127.0f;
    for (int u = tid; u < 1584; u += 512) {
        int r = u / 264, rem = u % 264, pix = rem >> 2, c4 = rem & 3;
        int hr = H0 + r - 1, wc = w0 + pix - 1;
        union { int8_t b[16]; int4 v; } pk;
        pk.v = make_int4(0, 0, 0, 0);
        if (hr >= 0 && hr < HH && wc >= 0 && wc < WW) {
            const float4* src = reinterpret_cast<const float4*>(
                &g_X1[(size_t)((n*HW + hr*WW + wc)*64 + c4*16)]);
            #pragma unroll
            for (int q2 = 0; q2 < 4; q2++) {
                float4 v = src[q2];
                int cb = c4*16 + q2*4;
                float vv[4] = {v.x, v.y, v.z, v.w};
                #pragma unroll
                for (int j = 0; j < 4; j++) {
                    float t = vv[j]*sc1[cb+j] + sb1[cb+j];
                    t = fminf(fmaxf(t, -al), al);
                    pk.b[q2*4 + j] = (int8_t)(int)rintf(t / sc);
                }
            }
        }
        sA[(r*66 + pix)*4 + (c4 ^ ((pix & 6) >> 1))] = pk.v;
    }
    for (int u = tid; u < 2304; u += 512) {
        int c4 = u & 3, co = (u >> 2) & 63, t = u >> 8;
        sW[(t*64 + co)*4 + (c4 ^ ((co & 6) >> 1))] = W4[u];
    }
    __syncthreads();

    int g = lane >> 2, t4 = lane & 3;
    int pg = warp >> 1, ch = warp & 1;
    int lrow = pg >> 1, colb = (pg & 1) * 32;

    int acc[2][4][4];
    #pragma unroll
    for (int mg = 0; mg < 2; mg++)
        #pragma unroll
        for (int o = 0; o < 4; o++)
            #pragma unroll
            for (int j = 0; j < 4; j++) acc[mg][o][j] = 0;

    #pragma unroll 1
    for (int t = 0; t < 9; t++) {
        int dh = t / 3, dw = t % 3;
        int rs = lrow + dh;
        uint32_t af[2][2][4];
        #pragma unroll
        for (int c = 0; c < 2; c++) {
            int cin = 32*c + 4*t4;
            #pragma unroll
            for (int mg = 0; mg < 2; mg++) {
                int p0 = colb + mg*16 + g + dw;
                int off = (rs*66 + p0)*16 + ((cin ^ ((p0 & 6) << 3)) >> 2);
                af[c][mg][0] = sAw[off];
                af[c][mg][1] = sAw[off + 128];
                af[c][mg][2] = sAw[off ^ 4];
                af[c][mg][3] = sAw[(off + 128) ^ 4];
            }
        }
        #pragma unroll
        for (int o = 0; o < 4; o++) {
            int co = ch*32 + o*8 + g;
            #pragma unroll
            for (int c = 0; c < 2; c++) {
                int cin = 32*c + 4*t4;
                int boff = (t*64 + co)*16 + ((cin ^ ((co & 6) << 3)) >> 2);
                uint32_t b0 = sWw[boff];
                uint32_t b1 = sWw[boff ^ 4];
                #pragma unroll
                for (int mg = 0; mg < 2; mg++) {
                    asm volatile(
                        "mma.sync.aligned.m16n8k32.row.col.s32.s8.s8.s32 "
                        "{%0,%1,%2,%3},{%4,%5,%6,%7},{%8,%9},{%0,%1,%2,%3};"
                        : "+r"(acc[mg][o][0]), "+r"(acc[mg][o][1]),
                          "+r"(acc[mg][o][2]), "+r"(acc[mg][o][3])
                        : "r"(af[c][mg][0]), "r"(af[c][mg][1]),
                          "r"(af[c][mg][2]), "r"(af[c][mg][3]),
                          "r"(b0), "r"(b1));
                }
            }
        }
    }

    float S = g_S[1];
    float sj[4][2], qj[4][2];
    #pragma unroll
    for (int o = 0; o < 4; o++) { sj[o][0]=sj[o][1]=qj[o][0]=qj[o][1]=0.f; }

    bool geven = (g & 1) == 0;
    #pragma unroll
    for (int mg = 0; mg < 2; mg++) {
        int pixl = (H0 + lrow)*WW + w0 + colb + mg*16;
        #pragma unroll
        for (int o = 0; o < 4; o++) {
            int col = ch*32 + o*8 + 2*t4;
            float y0 = S * (float)acc[mg][o][0];
            float y1 = S * (float)acc[mg][o][1];
            float y2 = S * (float)acc[mg][o][2];
            float y3 = S * (float)acc[mg][o][3];
            float y0n = __shfl_xor_sync(0xffffffffu, y0, 4);
            float y1n = __shfl_xor_sync(0xffffffffu, y1, 4);
            float y2n = __shfl_xor_sync(0xffffffffu, y2, 4);
            float y3n = __shfl_xor_sync(0xffffffffu, y3, 4);
            int b0 = (n*64 + col)*HW + pixl;
            int b1 = b0 + HW;
            int addrA = geven ? (b0 + g)     : (b1 + g - 1);
            int addrB = geven ? (b0 + 8 + g) : (b1 + 7 + g);
            __half2 vA = geven ? __floats2half2_rn(y0, y0n) : __floats2half2_rn(y1n, y1);
            __half2 vB = geven ? __floats2half2_rn(y2, y2n) : __floats2half2_rn(y3n, y3);
            *reinterpret_cast<__half2*>(&g_Y2h[addrA]) = vA;
            *reinterpret_cast<__half2*>(&g_Y2h[addrB]) = vB;
            sj[o][0] += y0 + y2;  qj[o][0] += y0*y0 + y2*y2;
            sj[o][1] += y1 + y3;  qj[o][1] += y1*y1 + y3*y3;
        }
    }
    #pragma unroll
    for (int o = 0; o < 4; o++) {
        #pragma unroll
        for (int j = 0; j < 2; j++) {
            float s = sj[o][j], q = qj[o][j];
            #pragma unroll
            for (int off = 4; off < 32; off <<= 1) {
                s += __shfl_xor_sync(0xffffffffu, s, off);
                q += __shfl_xor_sync(0xffffffffu, q, off);
            }
            if (g == 0) {
                int chan = ch*32 + o*8 + t4*2 + j;
                atomicAdd(&ss[chan], s);
                atomicAdd(&sq[chan], q);
            }
        }
    }
    __syncthreads();
    if (tid < 64) {
        atomicAdd(&g_bn2s[tid], (double)ss[tid]);
        atomicAdd(&g_bn2q[tid], (double)sq[tid]);
    }
}

// ---------------- BN stats finalize ----------------
template<bool FIRST>
__global__ void k_stats(const float* __restrict__ gamma, const float* __restrict__ beta)
{
    int c = threadIdx.x;
    const double* bs = FIRST ? g_bn1s : g_bn2s;
    const double* bq = FIRST ? g_bn1q : g_bn2q;
    double invn = 1.0 / (double)NPIX;
    double mean = bs[c] * invn;
    double var  = bq[c] * invn - mean*mean;
    float scl = gamma[c] * rsqrtf((float)var + 1e-5f);
    if (FIRST) { g_c1s[c] = scl; g_c1b[c] = beta[c] - (float)mean * scl; }
    else       { g_c2s[c] = scl; g_c2b[c] = beta[c] - (float)mean * scl; }
}

// ---------------- final elementwise, MLP=8 ----------------
__global__ void k_final(const float* __restrict__ idn, const float* __restrict__ shortcut,
                        float* __restrict__ out, const float* __restrict__ bits,
                        const float* __restrict__ f, const float* __restrict__ bout,
                        int out_size)
{
    int c = blockIdx.y, n = blockIdx.z;
    int base = ((n*CC + c)*HW >> 2) + blockIdx.x*1024 + threadIdx.x;   // float4 index
    float scl = g_c2s[c], sft = g_c2b[c], sh = shortcut[0];
    const uint2* Y2v = reinterpret_cast<const uint2*>(g_Y2h);
    const float4* I4 = reinterpret_cast<const float4*>(idn);
    float4* O4 = reinterpret_cast<float4*>(out);

    uint2 y[4];
    float4 v[4];
    #pragma unroll
    for (int k = 0; k < 4; k++) {
        int i = base + k*256;
        y[k] = Y2v[i];
        v[k] = I4[i];
    }
    #pragma unroll
    for (int k = 0; k < 4; k++) {
        __half2 ha = *reinterpret_cast<__half2*>(&y[k].x);
        __half2 hb = *reinterpret_cast<__half2*>(&y[k].y);
        float2 ya = __half22float2(ha);
        float2 yb = __half22float2(hb);
        float4 r;
        r.x = v[k].x*sh + ya.x*scl + sft;
        r.y = v[k].y*sh + ya.y*scl + sft;
        r.z = v[k].z*sh + yb.x*scl + sft;
        r.w = v[k].w*sh + yb.y*scl + sft;
        O4[base + k*256] = r;
    }
    if (blockIdx.x == 0 && blockIdx.y == 0 && blockIdx.z == 0 && threadIdx.x == 0
        && out_size >= VOL + 3) {
        out[VOL]   = bits[0];
        out[VOL+1] = f[0];
        out[VOL+2] = bout[0];
    }
}

// ---------------- launch ----------------
extern "C" void kernel_launch(void* const* d_in, const int* in_sizes, int n_in,
                              void* d_out, int out_size)
{
    (void)in_sizes; (void)n_in;
    const float* identity = (const float*)d_in[0];
    const float* bits     = (const float*)d_in[1];
    const float* f        = (const float*)d_in[2];
    const float* bits_out = (const float*)d_in[3];
    const float* w1       = (const float*)d_in[4];
    const float* w2       = (const float*)d_in[5];
    const float* alpha1   = (const float*)d_in[6];
    const float* alpha2   = (const float*)d_in[7];
    const float* gamma1   = (const float*)d_in[8];
    const float* beta1    = (const float*)d_in[9];
    const float* gamma2   = (const float*)d_in[10];
    const float* beta2    = (const float*)d_in[11];
    const float* prelu_a  = (const float*)d_in[12];
    const float* shortcut = (const float*)d_in[13];
    float* out = (float*)d_out;

    const int SMEM1 = (1056 + 2304) * 16;  // 53760 B  (conv1 hybrid, 2-row)
    const int SMEM2 = (1584 + 2304) * 16;  // 62208 B  (conv2 IMMA, 4-row)
    cudaFuncSetAttribute(k_conv1, cudaFuncAttributeMaxDynamicSharedMemorySize, SMEM1);
    cudaFuncSetAttribute(k_conv2, cudaFuncAttributeMaxDynamicSharedMemorySize, SMEM2);

    k_wquant<<<3, 256>>>(w1, w2, alpha1, alpha2);
    k_quant1<<<dim3(6,192,8), dim3(32,8)>>>(identity, alpha1);
    k_conv1<<<dim3(3,96,8), 384, SMEM1>>>(prelu_a);
    k_stats<true><<<1, 64>>>(gamma1, beta1);
    k_conv2<<<dim3(3,48,8), 512, SMEM2>>>(alpha2);
    k_stats<false><<<1, 64>>>(gamma2, beta2);
    k_final<<<dim3(HW/4/1024, CC, NB), 256>>>(identity, shortcut, out, bits, f, bits_out, out_size);
}